// round 13
// baseline (speedup 1.0000x reference)
#include <cuda_runtime.h>
#include <cstdint>

// Problem constants
#define NN_ 2048
#define BB_ 16
#define DD_ 8
#define TRACE_ROWS 16                     // gridDim.x(=2) * 16 = 32 trace blocks

static __device__ __constant__ const float kAlpha = 0.95122945f;
static __device__ __constant__ const float kOneMinusAlpha = 1.0f - 0.95122945f;

// Shared layout (dynamic): W stage [16][1024] floats, then s_pre[8][16], s_xd[8][16]
#define SW_FLOATS   (BB_ * 1024)          // 16384 floats = 64KB
#define SMEM_FLOATS (SW_FLOATS + 2 * DD_ * BB_)

#define CP_ASYNC16(smem_u32, gptr) \
    asm volatile("cp.async.cg.shared.global [%0], [%1], 16;" \
                 :: "r"(smem_u32), "l"(gptr) : "memory")
#define CP_COMMIT() asm volatile("cp.async.commit_group;" ::: "memory")
#define CP_WAIT(n)  asm volatile("cp.async.wait_group %0;" :: "n"(n) : "memory")

__device__ __forceinline__ uint32_t smem_u32(const void* p) {
    return (uint32_t)__cvta_generic_to_shared(p);
}

// ---------------------------------------------------------------------------
// Final kernel (converged):
//   - 2 staggered CTAs/SM (regs ~119 = RF boundary), launch-pipelined blocks
//   - W staged via cp.async ring, 8 commit-groups of 2 b-tiles, consume from
//     wait_group 7 (compute starts after first 8KB lands)
//   - dmap/A_p/A_d register-resident (b-invariant, read once per block)
//   - per-(e) scalars broadcast via smem
//   - trace-update stream fused as early grid.y rows
//   blockIdx.y <  TRACE_ROWS : trace-update elementwise stream (~3MB).
//   blockIdx.y >= TRACE_ROWS : main STDP update, e = blockIdx.y - TRACE_ROWS.
// ---------------------------------------------------------------------------
__global__ void __launch_bounds__(256, 2) stdp_fused(
    const float* __restrict__ Xd,        // [D,B,N]
    const float* __restrict__ Xpost,     // [B,N]
    const float* __restrict__ xbar_pre,  // [D,B,N]
    const float* __restrict__ xbar_post, // [B,N]
    const float* __restrict__ W,         // [B,N,N] (b,e,o)
    const float* __restrict__ A_p,       // [N,N]   (e,o)
    const float* __restrict__ A_d,       // [N,N]   (e,o)
    const float* __restrict__ dmap,      // [D,N,N] (d,e,o)
    float* __restrict__ out,             // [B,N,N]
    float* __restrict__ Wnew,            // [B,N,N]
    float* __restrict__ pre_out,         // [D,B,N]
    float* __restrict__ post_out)        // [B,N]
{
    extern __shared__ float sm[];
    float* s_w   = sm;                    // [16][1024]
    float* s_pre = sm + SW_FLOATS;        // [8][16]
    float* s_xd  = s_pre + DD_ * BB_;     // [8][16]

    if (blockIdx.y < TRACE_ROWS) {
        // ---- trace-update stream (scheduled early, overlaps main waves) ----
        const int vb = blockIdx.y * gridDim.x + blockIdx.x;   // 0..31
        const int tg = vb * 256 + threadIdx.x;
        const int npre = DD_ * BB_ * NN_ / 4;   // 65536
        const int ntot = npre + BB_ * NN_ / 4;  // 73728
        for (int i = tg; i < ntot; i += TRACE_ROWS * 2 * 256) {
            float4 x, xb;
            if (i < npre) {
                x  = reinterpret_cast<const float4*>(Xd)[i];
                xb = reinterpret_cast<const float4*>(xbar_pre)[i];
            } else {
                x  = reinterpret_cast<const float4*>(Xpost)[i - npre];
                xb = reinterpret_cast<const float4*>(xbar_post)[i - npre];
            }
            float4 r;
            r.x = fmaf(kAlpha, xb.x, kOneMinusAlpha * x.x);
            r.y = fmaf(kAlpha, xb.y, kOneMinusAlpha * x.y);
            r.z = fmaf(kAlpha, xb.z, kOneMinusAlpha * x.z);
            r.w = fmaf(kAlpha, xb.w, kOneMinusAlpha * x.w);
            if (i < npre) __stcs(reinterpret_cast<float4*>(pre_out) + i, r);
            else          __stcs(reinterpret_cast<float4*>(post_out) + (i - npre), r);
        }
        return;
    }

    // ---- main STDP path ----
    const int e = blockIdx.y - TRACE_ROWS;
    const int t = threadIdx.x;
    const int o = blockIdx.x * 1024 + t * 4;
    const size_t eo = (size_t)e * NN_ + o;

    // b-invariant planes FIRST (consumed earliest): register-resident for the
    // whole b-loop. This pins regs near 128 -> exactly 2 CTAs/SM; L1 cannot be
    // relied on here (smem carveout), so registers are the right home.
    float4 dm[DD_];
#pragma unroll
    for (int d = 0; d < DD_; d++)
        dm[d] = __ldcs(reinterpret_cast<const float4*>(dmap + (size_t)d * NN_ * NN_ + eo));
    const float4 ap = __ldcs(reinterpret_cast<const float4*>(A_p + eo));
    const float4 ad = __ldcs(reinterpret_cast<const float4*>(A_d + eo));

    // Async-stage all 16 W[b] tiles: 8 commit-groups of 2.
    const uint32_t swa = smem_u32(s_w + t * 4);
#pragma unroll
    for (int g = 0; g < 8; g++) {
#pragma unroll
        for (int j = 0; j < 2; j++) {
            const int b = g * 2 + j;
            CP_ASYNC16(swa + (uint32_t)b * 4096u, W + (size_t)b * NN_ * NN_ + eo);
        }
        CP_COMMIT();
    }

    // Per-(e) scalars.
    if (t < DD_ * BB_) {
        const int d = t >> 4, b = t & 15;
        s_pre[t] = xbar_pre[((size_t)d * BB_ + b) * NN_ + e];
    } else {
        const int i = t - DD_ * BB_;
        const int d = i >> 4, b = i & 15;
        s_xd[i] = Xd[((size_t)d * BB_ + b) * NN_ + e];
    }
    __syncthreads();

#define PROCESS2(B0)                                                            \
    {                                                                           \
        _Pragma("unroll")                                                       \
        for (int j = 0; j < 2; j++) {                                           \
            const int b = (B0) + j;                                             \
            float4 pot = make_float4(0.f, 0.f, 0.f, 0.f);                       \
            float4 dep = make_float4(0.f, 0.f, 0.f, 0.f);                       \
            _Pragma("unroll")                                                   \
            for (int d = 0; d < DD_; d++) {                                     \
                const float p = s_pre[d * BB_ + b];                             \
                pot.x = fmaf(dm[d].x, p, pot.x);                                \
                pot.y = fmaf(dm[d].y, p, pot.y);                                \
                pot.z = fmaf(dm[d].z, p, pot.z);                                \
                pot.w = fmaf(dm[d].w, p, pot.w);                                \
                const float q = s_xd[d * BB_ + b];                              \
                dep.x = fmaf(dm[d].x, q, dep.x);                                \
                dep.y = fmaf(dm[d].y, q, dep.y);                                \
                dep.z = fmaf(dm[d].z, q, dep.z);                                \
                dep.w = fmaf(dm[d].w, q, dep.w);                                \
            }                                                                   \
            const float4 xp = *reinterpret_cast<const float4*>(                 \
                Xpost + (size_t)b * NN_ + o);                                   \
            const float4 xb = *reinterpret_cast<const float4*>(                 \
                xbar_post + (size_t)b * NN_ + o);                               \
            const float4 w = *reinterpret_cast<const float4*>(                  \
                s_w + b * 1024 + t * 4);                                        \
            const size_t idx = (size_t)b * NN_ * NN_ + eo;                      \
            __stcs(reinterpret_cast<float4*>(out + idx), w);                    \
            float4 wn;                                                          \
            wn.x = fminf(fmaxf(fmaf(xp.x * ap.x, pot.x,                         \
                        fmaf(-xb.x * ad.x, dep.x, w.x)), 0.f), 1.f);            \
            wn.y = fminf(fmaxf(fmaf(xp.y * ap.y, pot.y,                         \
                        fmaf(-xb.y * ad.y, dep.y, w.y)), 0.f), 1.f);            \
            wn.z = fminf(fmaxf(fmaf(xp.z * ap.z, pot.z,                         \
                        fmaf(-xb.z * ad.z, dep.z, w.z)), 0.f), 1.f);            \
            wn.w = fminf(fmaxf(fmaf(xp.w * ap.w, pot.w,                         \
                        fmaf(-xb.w * ad.w, dep.w, w.w)), 0.f), 1.f);            \
            __stcs(reinterpret_cast<float4*>(Wnew + idx), wn);                  \
        }                                                                       \
    }

    CP_WAIT(7); PROCESS2(0);   // start as soon as group 0's 8KB lands
    CP_WAIT(6); PROCESS2(2);
    CP_WAIT(5); PROCESS2(4);
    CP_WAIT(4); PROCESS2(6);
    CP_WAIT(3); PROCESS2(8);
    CP_WAIT(2); PROCESS2(10);
    CP_WAIT(1); PROCESS2(12);
    CP_WAIT(0); PROCESS2(14);
#undef PROCESS2
}

extern "C" void kernel_launch(void* const* d_in, const int* in_sizes, int n_in,
                              void* d_out, int out_size)
{
    const float* Xd        = (const float*)d_in[0]; // (D,B,N)
    const float* Xpost     = (const float*)d_in[1]; // (B,N)
    const float* xbar_pre  = (const float*)d_in[2]; // (D,B,N)
    const float* xbar_post = (const float*)d_in[3]; // (B,N)
    const float* W         = (const float*)d_in[4]; // (B,N,N)
    const float* A_p       = (const float*)d_in[5]; // (N,N)
    const float* A_d       = (const float*)d_in[6]; // (N,N)
    const float* dmap      = (const float*)d_in[7]; // (D,N,N)

    float* out      = (float*)d_out;
    float* Wnew     = out  + (size_t)BB_ * NN_ * NN_;
    float* pre_out  = Wnew + (size_t)BB_ * NN_ * NN_;
    float* post_out = pre_out + (size_t)DD_ * BB_ * NN_;

    const int smem_bytes = SMEM_FLOATS * sizeof(float);   // ~66KB
    static int attr_set = 0;
    if (!attr_set) {
        cudaFuncSetAttribute(stdp_fused,
                             cudaFuncAttributeMaxDynamicSharedMemorySize,
                             smem_bytes);
        attr_set = 1;
    }

    dim3 grid(NN_ / (256 * 4), NN_ + TRACE_ROWS);   // (2, 2064)
    stdp_fused<<<grid, 256, smem_bytes>>>(
        Xd, Xpost, xbar_pre, xbar_post, W, A_p, A_d, dmap,
        out, Wnew, pre_out, post_out);
}

// round 14
// speedup vs baseline: 1.0013x; 1.0013x over previous
#include <cuda_runtime.h>
#include <cstdint>

// Problem constants
#define NN_ 2048
#define BB_ 16
#define DD_ 8
#define TRACE_ROWS 16                     // gridDim.x(=2) * 16 = 32 trace blocks

static __device__ __constant__ const float kAlpha = 0.95122945f;
static __device__ __constant__ const float kOneMinusAlpha = 1.0f - 0.95122945f;

// Shared layout (dynamic): W stage [16][1024] floats, then s_pre[8][16], s_xd[8][16]
#define SW_FLOATS   (BB_ * 1024)          // 16384 floats = 64KB
#define SMEM_FLOATS (SW_FLOATS + 2 * DD_ * BB_)

#define CP_ASYNC16(smem_u32, gptr) \
    asm volatile("cp.async.cg.shared.global [%0], [%1], 16;" \
                 :: "r"(smem_u32), "l"(gptr) : "memory")
#define CP_COMMIT() asm volatile("cp.async.commit_group;" ::: "memory")
#define CP_WAIT(n)  asm volatile("cp.async.wait_group %0;" :: "n"(n) : "memory")

__device__ __forceinline__ uint32_t smem_u32(const void* p) {
    return (uint32_t)__cvta_generic_to_shared(p);
}

// ---------------------------------------------------------------------------
// Final kernel (converged over 13 rounds; 434us -> 152us):
//   - 2 staggered CTAs/SM (regs ~119 = RF boundary), launch-pipelined blocks
//   - W staged via cp.async ring, 8 commit-groups of 2 b-tiles, consume from
//     wait_group 7 (compute starts after first 8KB lands)
//   - dmap/A_p/A_d register-resident (b-invariant, read once per block);
//     their LDG latency is shadowed by the cp.async pipeline fill
//   - per-(e) scalars broadcast via smem
//   - trace-update stream fused as early grid.y rows
//   blockIdx.y <  TRACE_ROWS : trace-update elementwise stream (~3MB).
//   blockIdx.y >= TRACE_ROWS : main STDP update, e = blockIdx.y - TRACE_ROWS.
// ---------------------------------------------------------------------------
__global__ void __launch_bounds__(256, 2) stdp_fused(
    const float* __restrict__ Xd,        // [D,B,N]
    const float* __restrict__ Xpost,     // [B,N]
    const float* __restrict__ xbar_pre,  // [D,B,N]
    const float* __restrict__ xbar_post, // [B,N]
    const float* __restrict__ W,         // [B,N,N] (b,e,o)
    const float* __restrict__ A_p,       // [N,N]   (e,o)
    const float* __restrict__ A_d,       // [N,N]   (e,o)
    const float* __restrict__ dmap,      // [D,N,N] (d,e,o)
    float* __restrict__ out,             // [B,N,N]
    float* __restrict__ Wnew,            // [B,N,N]
    float* __restrict__ pre_out,         // [D,B,N]
    float* __restrict__ post_out)        // [B,N]
{
    extern __shared__ float sm[];
    float* s_w   = sm;                    // [16][1024]
    float* s_pre = sm + SW_FLOATS;        // [8][16]
    float* s_xd  = s_pre + DD_ * BB_;     // [8][16]

    if (blockIdx.y < TRACE_ROWS) {
        // ---- trace-update stream (scheduled early, overlaps main waves) ----
        const int vb = blockIdx.y * gridDim.x + blockIdx.x;   // 0..31
        const int tg = vb * 256 + threadIdx.x;
        const int npre = DD_ * BB_ * NN_ / 4;   // 65536
        const int ntot = npre + BB_ * NN_ / 4;  // 73728
        for (int i = tg; i < ntot; i += TRACE_ROWS * 2 * 256) {
            float4 x, xb;
            if (i < npre) {
                x  = reinterpret_cast<const float4*>(Xd)[i];
                xb = reinterpret_cast<const float4*>(xbar_pre)[i];
            } else {
                x  = reinterpret_cast<const float4*>(Xpost)[i - npre];
                xb = reinterpret_cast<const float4*>(xbar_post)[i - npre];
            }
            float4 r;
            r.x = fmaf(kAlpha, xb.x, kOneMinusAlpha * x.x);
            r.y = fmaf(kAlpha, xb.y, kOneMinusAlpha * x.y);
            r.z = fmaf(kAlpha, xb.z, kOneMinusAlpha * x.z);
            r.w = fmaf(kAlpha, xb.w, kOneMinusAlpha * x.w);
            if (i < npre) __stcs(reinterpret_cast<float4*>(pre_out) + i, r);
            else          __stcs(reinterpret_cast<float4*>(post_out) + (i - npre), r);
        }
        return;
    }

    // ---- main STDP path ----
    const int e = blockIdx.y - TRACE_ROWS;
    const int t = threadIdx.x;
    const int o = blockIdx.x * 1024 + t * 4;
    const size_t eo = (size_t)e * NN_ + o;

    // b-invariant planes FIRST (consumed earliest): register-resident for the
    // whole b-loop. This pins regs near 128 -> exactly 2 CTAs/SM; L1 cannot be
    // relied on here (smem carveout), so registers are the right home.
    float4 dm[DD_];
#pragma unroll
    for (int d = 0; d < DD_; d++)
        dm[d] = __ldcs(reinterpret_cast<const float4*>(dmap + (size_t)d * NN_ * NN_ + eo));
    const float4 ap = __ldcs(reinterpret_cast<const float4*>(A_p + eo));
    const float4 ad = __ldcs(reinterpret_cast<const float4*>(A_d + eo));

    // Async-stage all 16 W[b] tiles: 8 commit-groups of 2.
    const uint32_t swa = smem_u32(s_w + t * 4);
#pragma unroll
    for (int g = 0; g < 8; g++) {
#pragma unroll
        for (int j = 0; j < 2; j++) {
            const int b = g * 2 + j;
            CP_ASYNC16(swa + (uint32_t)b * 4096u, W + (size_t)b * NN_ * NN_ + eo);
        }
        CP_COMMIT();
    }

    // Per-(e) scalars.
    if (t < DD_ * BB_) {
        const int d = t >> 4, b = t & 15;
        s_pre[t] = xbar_pre[((size_t)d * BB_ + b) * NN_ + e];
    } else {
        const int i = t - DD_ * BB_;
        const int d = i >> 4, b = i & 15;
        s_xd[i] = Xd[((size_t)d * BB_ + b) * NN_ + e];
    }
    __syncthreads();

#define PROCESS2(B0)                                                            \
    {                                                                           \
        _Pragma("unroll")                                                       \
        for (int j = 0; j < 2; j++) {                                           \
            const int b = (B0) + j;                                             \
            float4 pot = make_float4(0.f, 0.f, 0.f, 0.f);                       \
            float4 dep = make_float4(0.f, 0.f, 0.f, 0.f);                       \
            _Pragma("unroll")                                                   \
            for (int d = 0; d < DD_; d++) {                                     \
                const float p = s_pre[d * BB_ + b];                             \
                pot.x = fmaf(dm[d].x, p, pot.x);                                \
                pot.y = fmaf(dm[d].y, p, pot.y);                                \
                pot.z = fmaf(dm[d].z, p, pot.z);                                \
                pot.w = fmaf(dm[d].w, p, pot.w);                                \
                const float q = s_xd[d * BB_ + b];                              \
                dep.x = fmaf(dm[d].x, q, dep.x);                                \
                dep.y = fmaf(dm[d].y, q, dep.y);                                \
                dep.z = fmaf(dm[d].z, q, dep.z);                                \
                dep.w = fmaf(dm[d].w, q, dep.w);                                \
            }                                                                   \
            const float4 xp = *reinterpret_cast<const float4*>(                 \
                Xpost + (size_t)b * NN_ + o);                                   \
            const float4 xb = *reinterpret_cast<const float4*>(                 \
                xbar_post + (size_t)b * NN_ + o);                               \
            const float4 w = *reinterpret_cast<const float4*>(                  \
                s_w + b * 1024 + t * 4);                                        \
            const size_t idx = (size_t)b * NN_ * NN_ + eo;                      \
            __stcs(reinterpret_cast<float4*>(out + idx), w);                    \
            float4 wn;                                                          \
            wn.x = fminf(fmaxf(fmaf(xp.x * ap.x, pot.x,                         \
                        fmaf(-xb.x * ad.x, dep.x, w.x)), 0.f), 1.f);            \
            wn.y = fminf(fmaxf(fmaf(xp.y * ap.y, pot.y,                         \
                        fmaf(-xb.y * ad.y, dep.y, w.y)), 0.f), 1.f);            \
            wn.z = fminf(fmaxf(fmaf(xp.z * ap.z, pot.z,                         \
                        fmaf(-xb.z * ad.z, dep.z, w.z)), 0.f), 1.f);            \
            wn.w = fminf(fmaxf(fmaf(xp.w * ap.w, pot.w,                         \
                        fmaf(-xb.w * ad.w, dep.w, w.w)), 0.f), 1.f);            \
            __stcs(reinterpret_cast<float4*>(Wnew + idx), wn);                  \
        }                                                                       \
    }

    CP_WAIT(7); PROCESS2(0);   // start as soon as group 0's 8KB lands
    CP_WAIT(6); PROCESS2(2);
    CP_WAIT(5); PROCESS2(4);
    CP_WAIT(4); PROCESS2(6);
    CP_WAIT(3); PROCESS2(8);
    CP_WAIT(2); PROCESS2(10);
    CP_WAIT(1); PROCESS2(12);
    CP_WAIT(0); PROCESS2(14);
#undef PROCESS2
}

extern "C" void kernel_launch(void* const* d_in, const int* in_sizes, int n_in,
                              void* d_out, int out_size)
{
    const float* Xd        = (const float*)d_in[0]; // (D,B,N)
    const float* Xpost     = (const float*)d_in[1]; // (B,N)
    const float* xbar_pre  = (const float*)d_in[2]; // (D,B,N)
    const float* xbar_post = (const float*)d_in[3]; // (B,N)
    const float* W         = (const float*)d_in[4]; // (B,N,N)
    const float* A_p       = (const float*)d_in[5]; // (N,N)
    const float* A_d       = (const float*)d_in[6]; // (N,N)
    const float* dmap      = (const float*)d_in[7]; // (D,N,N)

    float* out      = (float*)d_out;
    float* Wnew     = out  + (size_t)BB_ * NN_ * NN_;
    float* pre_out  = Wnew + (size_t)BB_ * NN_ * NN_;
    float* post_out = pre_out + (size_t)DD_ * BB_ * NN_;

    const int smem_bytes = SMEM_FLOATS * sizeof(float);   // ~66KB
    static int attr_set = 0;
    if (!attr_set) {
        cudaFuncSetAttribute(stdp_fused,
                             cudaFuncAttributeMaxDynamicSharedMemorySize,
                             smem_bytes);
        attr_set = 1;
    }

    dim3 grid(NN_ / (256 * 4), NN_ + TRACE_ROWS);   // (2, 2064)
    stdp_fused<<<grid, 256, smem_bytes>>>(
        Xd, Xpost, xbar_pre, xbar_post, W, A_p, A_d, dmap,
        out, Wnew, pre_out, post_out);
}

// round 15
// speedup vs baseline: 1.0103x; 1.0090x over previous
#include <cuda_runtime.h>
#include <cstdint>

// Problem constants
#define NN_ 2048
#define BB_ 16
#define DD_ 8
#define TRACE_ROWS 16                     // gridDim.x(=2) * 16 = 32 trace blocks

static __device__ __constant__ const float kAlpha = 0.95122945f;
static __device__ __constant__ const float kOneMinusAlpha = 1.0f - 0.95122945f;

// Shared layout (dynamic): W stage [16][1024] floats, then s_pre[8][16], s_xd[8][16]
#define SW_FLOATS   (BB_ * 1024)          // 16384 floats = 64KB
#define SMEM_FLOATS (SW_FLOATS + 2 * DD_ * BB_)

#define CP_ASYNC16(smem_u32, gptr) \
    asm volatile("cp.async.cg.shared.global [%0], [%1], 16;" \
                 :: "r"(smem_u32), "l"(gptr) : "memory")
#define CP_COMMIT() asm volatile("cp.async.commit_group;" ::: "memory")
#define CP_WAIT(n)  asm volatile("cp.async.wait_group %0;" :: "n"(n) : "memory")

__device__ __forceinline__ uint32_t smem_u32(const void* p) {
    return (uint32_t)__cvta_generic_to_shared(p);
}

// ---------------------------------------------------------------------------
// Final kernel (converged over 14 rounds; 434us -> 152us, ~78% of HBM spec,
// traffic at the 928MB mandatory floor):
//   - 2 staggered CTAs/SM (regs ~119 = RF boundary), launch-pipelined blocks
//   - W staged via cp.async ring, 8 commit-groups of 2 b-tiles, consume from
//     wait_group 7 (compute starts after first 8KB lands)
//   - dmap/A_p/A_d register-resident (b-invariant, read once per block);
//     their LDG latency is shadowed by the cp.async pipeline fill
//   - per-(e) scalars broadcast via smem
//   - trace-update stream fused as early grid.y rows
//   blockIdx.y <  TRACE_ROWS : trace-update elementwise stream (~3MB).
//   blockIdx.y >= TRACE_ROWS : main STDP update, e = blockIdx.y - TRACE_ROWS.
// ---------------------------------------------------------------------------
__global__ void __launch_bounds__(256, 2) stdp_fused(
    const float* __restrict__ Xd,        // [D,B,N]
    const float* __restrict__ Xpost,     // [B,N]
    const float* __restrict__ xbar_pre,  // [D,B,N]
    const float* __restrict__ xbar_post, // [B,N]
    const float* __restrict__ W,         // [B,N,N] (b,e,o)
    const float* __restrict__ A_p,       // [N,N]   (e,o)
    const float* __restrict__ A_d,       // [N,N]   (e,o)
    const float* __restrict__ dmap,      // [D,N,N] (d,e,o)
    float* __restrict__ out,             // [B,N,N]
    float* __restrict__ Wnew,            // [B,N,N]
    float* __restrict__ pre_out,         // [D,B,N]
    float* __restrict__ post_out)        // [B,N]
{
    extern __shared__ float sm[];
    float* s_w   = sm;                    // [16][1024]
    float* s_pre = sm + SW_FLOATS;        // [8][16]
    float* s_xd  = s_pre + DD_ * BB_;     // [8][16]

    if (blockIdx.y < TRACE_ROWS) {
        // ---- trace-update stream (scheduled early, overlaps main waves) ----
        const int vb = blockIdx.y * gridDim.x + blockIdx.x;   // 0..31
        const int tg = vb * 256 + threadIdx.x;
        const int npre = DD_ * BB_ * NN_ / 4;   // 65536
        const int ntot = npre + BB_ * NN_ / 4;  // 73728
        for (int i = tg; i < ntot; i += TRACE_ROWS * 2 * 256) {
            float4 x, xb;
            if (i < npre) {
                x  = reinterpret_cast<const float4*>(Xd)[i];
                xb = reinterpret_cast<const float4*>(xbar_pre)[i];
            } else {
                x  = reinterpret_cast<const float4*>(Xpost)[i - npre];
                xb = reinterpret_cast<const float4*>(xbar_post)[i - npre];
            }
            float4 r;
            r.x = fmaf(kAlpha, xb.x, kOneMinusAlpha * x.x);
            r.y = fmaf(kAlpha, xb.y, kOneMinusAlpha * x.y);
            r.z = fmaf(kAlpha, xb.z, kOneMinusAlpha * x.z);
            r.w = fmaf(kAlpha, xb.w, kOneMinusAlpha * x.w);
            if (i < npre) __stcs(reinterpret_cast<float4*>(pre_out) + i, r);
            else          __stcs(reinterpret_cast<float4*>(post_out) + (i - npre), r);
        }
        return;
    }

    // ---- main STDP path ----
    const int e = blockIdx.y - TRACE_ROWS;
    const int t = threadIdx.x;
    const int o = blockIdx.x * 1024 + t * 4;
    const size_t eo = (size_t)e * NN_ + o;

    // b-invariant planes FIRST (consumed earliest): register-resident for the
    // whole b-loop. This pins regs near 128 -> exactly 2 CTAs/SM; L1 cannot be
    // relied on here (smem carveout), so registers are the right home.
    float4 dm[DD_];
#pragma unroll
    for (int d = 0; d < DD_; d++)
        dm[d] = __ldcs(reinterpret_cast<const float4*>(dmap + (size_t)d * NN_ * NN_ + eo));
    const float4 ap = __ldcs(reinterpret_cast<const float4*>(A_p + eo));
    const float4 ad = __ldcs(reinterpret_cast<const float4*>(A_d + eo));

    // Async-stage all 16 W[b] tiles: 8 commit-groups of 2.
    const uint32_t swa = smem_u32(s_w + t * 4);
#pragma unroll
    for (int g = 0; g < 8; g++) {
#pragma unroll
        for (int j = 0; j < 2; j++) {
            const int b = g * 2 + j;
            CP_ASYNC16(swa + (uint32_t)b * 4096u, W + (size_t)b * NN_ * NN_ + eo);
        }
        CP_COMMIT();
    }

    // Per-(e) scalars.
    if (t < DD_ * BB_) {
        const int d = t >> 4, b = t & 15;
        s_pre[t] = xbar_pre[((size_t)d * BB_ + b) * NN_ + e];
    } else {
        const int i = t - DD_ * BB_;
        const int d = i >> 4, b = i & 15;
        s_xd[i] = Xd[((size_t)d * BB_ + b) * NN_ + e];
    }
    __syncthreads();

#define PROCESS2(B0)                                                            \
    {                                                                           \
        _Pragma("unroll")                                                       \
        for (int j = 0; j < 2; j++) {                                           \
            const int b = (B0) + j;                                             \
            float4 pot = make_float4(0.f, 0.f, 0.f, 0.f);                       \
            float4 dep = make_float4(0.f, 0.f, 0.f, 0.f);                       \
            _Pragma("unroll")                                                   \
            for (int d = 0; d < DD_; d++) {                                     \
                const float p = s_pre[d * BB_ + b];                             \
                pot.x = fmaf(dm[d].x, p, pot.x);                                \
                pot.y = fmaf(dm[d].y, p, pot.y);                                \
                pot.z = fmaf(dm[d].z, p, pot.z);                                \
                pot.w = fmaf(dm[d].w, p, pot.w);                                \
                const float q = s_xd[d * BB_ + b];                              \
                dep.x = fmaf(dm[d].x, q, dep.x);                                \
                dep.y = fmaf(dm[d].y, q, dep.y);                                \
                dep.z = fmaf(dm[d].z, q, dep.z);                                \
                dep.w = fmaf(dm[d].w, q, dep.w);                                \
            }                                                                   \
            const float4 xp = *reinterpret_cast<const float4*>(                 \
                Xpost + (size_t)b * NN_ + o);                                   \
            const float4 xb = *reinterpret_cast<const float4*>(                 \
                xbar_post + (size_t)b * NN_ + o);                               \
            const float4 w = *reinterpret_cast<const float4*>(                  \
                s_w + b * 1024 + t * 4);                                        \
            const size_t idx = (size_t)b * NN_ * NN_ + eo;                      \
            __stcs(reinterpret_cast<float4*>(out + idx), w);                    \
            float4 wn;                                                          \
            wn.x = fminf(fmaxf(fmaf(xp.x * ap.x, pot.x,                         \
                        fmaf(-xb.x * ad.x, dep.x, w.x)), 0.f), 1.f);            \
            wn.y = fminf(fmaxf(fmaf(xp.y * ap.y, pot.y,                         \
                        fmaf(-xb.y * ad.y, dep.y, w.y)), 0.f), 1.f);            \
            wn.z = fminf(fmaxf(fmaf(xp.z * ap.z, pot.z,                         \
                        fmaf(-xb.z * ad.z, dep.z, w.z)), 0.f), 1.f);            \
            wn.w = fminf(fmaxf(fmaf(xp.w * ap.w, pot.w,                         \
                        fmaf(-xb.w * ad.w, dep.w, w.w)), 0.f), 1.f);            \
            __stcs(reinterpret_cast<float4*>(Wnew + idx), wn);                  \
        }                                                                       \
    }

    CP_WAIT(7); PROCESS2(0);   // start as soon as group 0's 8KB lands
    CP_WAIT(6); PROCESS2(2);
    CP_WAIT(5); PROCESS2(4);
    CP_WAIT(4); PROCESS2(6);
    CP_WAIT(3); PROCESS2(8);
    CP_WAIT(2); PROCESS2(10);
    CP_WAIT(1); PROCESS2(12);
    CP_WAIT(0); PROCESS2(14);
#undef PROCESS2
}

extern "C" void kernel_launch(void* const* d_in, const int* in_sizes, int n_in,
                              void* d_out, int out_size)
{
    const float* Xd        = (const float*)d_in[0]; // (D,B,N)
    const float* Xpost     = (const float*)d_in[1]; // (B,N)
    const float* xbar_pre  = (const float*)d_in[2]; // (D,B,N)
    const float* xbar_post = (const float*)d_in[3]; // (B,N)
    const float* W         = (const float*)d_in[4]; // (B,N,N)
    const float* A_p       = (const float*)d_in[5]; // (N,N)
    const float* A_d       = (const float*)d_in[6]; // (N,N)
    const float* dmap      = (const float*)d_in[7]; // (D,N,N)

    float* out      = (float*)d_out;
    float* Wnew     = out  + (size_t)BB_ * NN_ * NN_;
    float* pre_out  = Wnew + (size_t)BB_ * NN_ * NN_;
    float* post_out = pre_out + (size_t)DD_ * BB_ * NN_;

    const int smem_bytes = SMEM_FLOATS * sizeof(float);   // ~66KB
    static int attr_set = 0;
    if (!attr_set) {
        cudaFuncSetAttribute(stdp_fused,
                             cudaFuncAttributeMaxDynamicSharedMemorySize,
                             smem_bytes);
        attr_set = 1;
    }

    dim3 grid(NN_ / (256 * 4), NN_ + TRACE_ROWS);   // (2, 2064)
    stdp_fused<<<grid, 256, smem_bytes>>>(
        Xd, Xpost, xbar_pre, xbar_post, W, A_p, A_d, dmap,
        out, Wnew, pre_out, post_out);
}